// round 1
// baseline (speedup 1.0000x reference)
#include <cuda_runtime.h>

// Problem constants (fixed shapes)
#define BB 8
#define CC 64
#define SS 16
#define HH 256
#define WW 256
#define HWN 65536
#define NCHUNK 128          // reduction chunks per batch (512 px each)
#define PART_STRIDE 1296    // 256 gram + 1024 G + 16 r

// ---------------- device scratch (no allocations allowed) ----------------
__device__ __align__(16) float g_U[BB * SS * HWN];              // conv1 output (33.5 MB)
__device__ __align__(16) float g_part[BB * NCHUNK * PART_STRIDE];
__device__ __align__(16) float g_PF2[BB * SS * CC];
__device__ __align__(16) float g_Wt_sub[128 * 9 * 16];          // [ic*9+tap][oc]
__device__ __align__(16) float g_Wt_cb[128 * 9 * 64];

// ---------------- weight pre-transpose: [oc][ic][tap] -> [ic*9+tap][oc] ----------------
__global__ void transpose_w_kernel(const float* __restrict__ Ws,
                                   const float* __restrict__ Wc) {
    int idx = blockIdx.x * 256 + threadIdx.x;
    if (idx < 16 * 1152) {
        int oc = idx / 1152; int r = idx - oc * 1152;
        g_Wt_sub[r * 16 + oc] = Ws[idx];
    }
    if (idx < 64 * 1152) {
        int oc = idx / 1152; int r = idx - oc * 1152;
        g_Wt_cb[r * 64 + oc] = Wc[idx];
    }
}

// ---------------- conv1: U = conv3x3(cat(x,bridge), W_sub), 128->16 ----------------
// tile 32x32 pixels, 256 threads, each thread: 4 rows x 1 col x 16 oc
__global__ __launch_bounds__(256, 2)
void conv1_kernel(const float* __restrict__ x, const float* __restrict__ bridge) {
    __shared__ __align__(16) float sIn[8][34][36];
    __shared__ __align__(16) float sW[8][9][16];

    int b = blockIdx.z;
    int by0 = blockIdx.y * 32, bx0 = blockIdx.x * 32;
    int tid = threadIdx.x;
    int pcol = tid & 31;
    int prow = tid >> 5;          // 0..7
    int ybase = prow * 4;

    float acc[4][16];
#pragma unroll
    for (int d = 0; d < 4; d++)
#pragma unroll
        for (int o = 0; o < 16; o++) acc[d][o] = 0.f;

    for (int k = 0; k < 16; k++) {
        const float* src = (k < 8) ? x : bridge;
        int cb = (k & 7) * 8;
        // stage 8-channel input tile with halo
        for (int idx = tid; idx < 8 * 34 * 34; idx += 256) {
            int c = idx / 1156; int rem = idx - c * 1156;
            int r = rem / 34;   int cc2 = rem - r * 34;
            int gy = by0 - 1 + r, gx = bx0 - 1 + cc2;
            float v = 0.f;
            if (gy >= 0 && gy < HH && gx >= 0 && gx < WW)
                v = src[(size_t)(b * 64 + cb + c) * HWN + gy * WW + gx];
            sIn[c][r][cc2] = v;
        }
        // stage weights (contiguous chunk of pre-transposed layout)
        for (int idx = tid; idx < 1152; idx += 256)
            ((float*)sW)[idx] = g_Wt_sub[k * 1152 + idx];
        __syncthreads();

#pragma unroll
        for (int c = 0; c < 8; c++) {
#pragma unroll
            for (int ky = 0; ky < 3; ky++) {
#pragma unroll
                for (int kx = 0; kx < 3; kx++) {
                    float iv0 = sIn[c][ybase + ky + 0][pcol + kx];
                    float iv1 = sIn[c][ybase + ky + 1][pcol + kx];
                    float iv2 = sIn[c][ybase + ky + 2][pcol + kx];
                    float iv3 = sIn[c][ybase + ky + 3][pcol + kx];
                    const float4* wp = reinterpret_cast<const float4*>(&sW[c][ky * 3 + kx][0]);
                    float wv[16];
                    *reinterpret_cast<float4*>(&wv[0])  = wp[0];
                    *reinterpret_cast<float4*>(&wv[4])  = wp[1];
                    *reinterpret_cast<float4*>(&wv[8])  = wp[2];
                    *reinterpret_cast<float4*>(&wv[12]) = wp[3];
#pragma unroll
                    for (int o = 0; o < 16; o++) {
                        acc[0][o] += iv0 * wv[o];
                        acc[1][o] += iv1 * wv[o];
                        acc[2][o] += iv2 * wv[o];
                        acc[3][o] += iv3 * wv[o];
                    }
                }
            }
        }
        __syncthreads();
    }

#pragma unroll
    for (int d = 0; d < 4; d++) {
        int y = by0 + ybase + d;
        int xg = bx0 + pcol;
#pragma unroll
        for (int s2 = 0; s2 < 16; s2++)
            g_U[((b * 16 + s2) << 16) + (y << 8) + xg] = acc[d][s2];
    }
}

// ---------------- reduction: Gram[16,16], G[16,64], r[16] partials per 512-px chunk ----------------
__global__ __launch_bounds__(256)
void reduce_kernel(const float* __restrict__ bridge) {
    __shared__ __align__(16) float sU[16][68];
    __shared__ __align__(16) float sB[64][68];

    int b = blockIdx.y, ch = blockIdx.x;
    int tid = threadIdx.x;
    int s = tid >> 4, q = tid & 15;
    int n0 = ch * 512;

    const float* Ub = g_U + (size_t)b * 16 * HWN;
    const float* Bb = bridge + (size_t)b * 64 * HWN;

    float accG[4] = {0.f, 0.f, 0.f, 0.f};
    float accM = 0.f;
    float accR = 0.f;

    for (int sub = 0; sub < 8; sub++) {
        int n = n0 + sub * 64;
        {
            int sl = tid >> 4, p4 = (tid & 15) * 4;
            *reinterpret_cast<float4*>(&sU[sl][p4]) =
                *reinterpret_cast<const float4*>(&Ub[sl * HWN + n + p4]);
        }
#pragma unroll
        for (int r = 0; r < 4; r++) {
            int cl = (tid >> 4) + r * 16;
            int p4 = (tid & 15) * 4;
            *reinterpret_cast<float4*>(&sB[cl][p4]) =
                *reinterpret_cast<const float4*>(&Bb[cl * HWN + n + p4]);
        }
        __syncthreads();
#pragma unroll
        for (int p = 0; p < 64; p += 4) {
            float4 u  = *reinterpret_cast<float4*>(&sU[s][p]);
            float4 t4 = *reinterpret_cast<float4*>(&sU[q][p]);
            accM += u.x * t4.x + u.y * t4.y + u.z * t4.z + u.w * t4.w;
#pragma unroll
            for (int j = 0; j < 4; j++) {
                float4 bv = *reinterpret_cast<float4*>(&sB[q + j * 16][p]);
                accG[j] += u.x * bv.x + u.y * bv.y + u.z * bv.z + u.w * bv.w;
            }
            if (q == 0)
                accR += fabsf(u.x) + fabsf(u.y) + fabsf(u.z) + fabsf(u.w);
        }
        __syncthreads();
    }

    float* out = g_part + (size_t)(b * NCHUNK + ch) * PART_STRIDE;
    out[s * 16 + q] = accM;
#pragma unroll
    for (int j = 0; j < 4; j++)
        out[256 + s * 64 + q + j * 16] = accG[j];
    if (q == 0) out[1280 + s] = accR;
}

// ---------------- solve: mat = D^-1 Gram D^-1; PF2 = D^-1 mat^-1 D^-1 G ----------------
__global__ __launch_bounds__(256)
void solve_kernel() {
    __shared__ float sGram[256];
    __shared__ float sG[1024];
    __shared__ float srr[16];
    __shared__ double A[16][17];
    __shared__ double M[16][17];
    __shared__ double spiv;

    int b = blockIdx.x;
    int tid = threadIdx.x;
    const float* base = g_part + (size_t)b * NCHUNK * PART_STRIDE;

    {
        float a = 0.f;
        for (int ch = 0; ch < NCHUNK; ch++) a += base[ch * PART_STRIDE + tid];
        sGram[tid] = a;
    }
#pragma unroll
    for (int j = 0; j < 4; j++) {
        int e = tid + j * 256;
        float a = 0.f;
        for (int ch = 0; ch < NCHUNK; ch++) a += base[ch * PART_STRIDE + 256 + e];
        sG[e] = a;
    }
    if (tid < 16) {
        float a = 0.f;
        for (int ch = 0; ch < NCHUNK; ch++) a += base[ch * PART_STRIDE + 1280 + tid];
        srr[tid] = 1e-6f + a;
    }
    __syncthreads();

    {
        int i = tid >> 4, t = tid & 15;
        A[i][t] = (double)sGram[tid] / ((double)srr[i] * (double)srr[t]);
        M[i][t] = (i == t) ? 1.0 : 0.0;
    }
    __syncthreads();

    // Gauss-Jordan (SPD, no pivoting), parallel over 256 threads
    for (int k = 0; k < 16; k++) {
        if (tid == 0) spiv = 1.0 / A[k][k];
        __syncthreads();
        if (tid < 16) { A[k][tid] *= spiv; M[k][tid] *= spiv; }
        __syncthreads();
        int i = tid >> 4, t = tid & 15;
        double f = A[i][k];
        __syncthreads();
        if (i != k) {
            A[i][t] -= f * A[k][t];
            M[i][t] -= f * M[k][t];
        }
        __syncthreads();
    }

#pragma unroll
    for (int j = 0; j < 4; j++) {
        int e = tid + j * 256;
        int s = e >> 6, c = e & 63;
        double v = 0.0;
#pragma unroll
        for (int t = 0; t < 16; t++)
            v += M[s][t] * ((double)sG[t * 64 + c] / (double)srr[t]);
        g_PF2[b * 1024 + e] = (float)(v / (double)srr[s]);
    }
}

// ---------------- conv2 (fused): out = conv3x3(cat(x, U^T*PF2), W_cb) + x ----------------
// tile 16x16 pixels, 256 threads = 4 oc-groups x 64 pixel-slots (4 rows each)
__global__ __launch_bounds__(256, 2)
void conv2_kernel(const float* __restrict__ x, float* __restrict__ out) {
    __shared__ float sU[16][18][20];
    __shared__ float sInC[4][18][20];
    __shared__ __align__(16) float sWC[4][9][64];
    __shared__ float sPF[1024];

    int b = blockIdx.z;
    int by0 = blockIdx.y * 16, bx0 = blockIdx.x * 16;
    int tid = threadIdx.x;
    int pcol = tid & 15;
    int prow = (tid >> 4) & 3;
    int g = tid >> 6;             // oc group 0..3
    int ybase = prow * 4;

    for (int idx = tid; idx < 1024; idx += 256) sPF[idx] = g_PF2[b * 1024 + idx];
    for (int idx = tid; idx < 16 * 324; idx += 256) {
        int s2 = idx / 324; int rem = idx - s2 * 324;
        int r = rem / 18;   int cc2 = rem - r * 18;
        int gy = by0 - 1 + r, gx = bx0 - 1 + cc2;
        float v = 0.f;
        if (gy >= 0 && gy < HH && gx >= 0 && gx < WW)
            v = g_U[((b * 16 + s2) << 16) + (gy << 8) + gx];
        sU[s2][r][cc2] = v;
    }

    float acc[4][16];
#pragma unroll
    for (int d = 0; d < 4; d++)
#pragma unroll
        for (int o = 0; o < 16; o++) acc[d][o] = 0.f;
    __syncthreads();

    for (int k = 0; k < 32; k++) {
        // weights: contiguous chunk
        for (int idx = tid; idx < 2304; idx += 256)
            ((float*)sWC)[idx] = g_Wt_cb[k * 2304 + idx];
        if (k < 16) {
            int cb = k * 4;
            for (int idx = tid; idx < 4 * 324; idx += 256) {
                int c = idx / 324; int rem = idx - c * 324;
                int r = rem / 18;  int cc2 = rem - r * 18;
                int gy = by0 - 1 + r, gx = bx0 - 1 + cc2;
                float v = 0.f;
                if (gy >= 0 && gy < HH && gx >= 0 && gx < WW)
                    v = x[(size_t)(b * 64 + cb + c) * HWN + gy * WW + gx];
                sInC[c][r][cc2] = v;
            }
        } else {
            int cpb = (k - 16) * 4;  // projected-channel base
            for (int idx = tid; idx < 4 * 324; idx += 256) {
                int c = idx / 324; int rem = idx - c * 324;
                int r = rem / 18;  int cc2 = rem - r * 18;
                float v = 0.f;
#pragma unroll
                for (int s2 = 0; s2 < 16; s2++)
                    v += sU[s2][r][cc2] * sPF[s2 * 64 + cpb + c];
                sInC[c][r][cc2] = v;
            }
        }
        __syncthreads();

#pragma unroll
        for (int c = 0; c < 4; c++) {
#pragma unroll
            for (int ky = 0; ky < 3; ky++) {
#pragma unroll
                for (int kx = 0; kx < 3; kx++) {
                    float iv0 = sInC[c][ybase + ky + 0][pcol + kx];
                    float iv1 = sInC[c][ybase + ky + 1][pcol + kx];
                    float iv2 = sInC[c][ybase + ky + 2][pcol + kx];
                    float iv3 = sInC[c][ybase + ky + 3][pcol + kx];
                    const float4* wp =
                        reinterpret_cast<const float4*>(&sWC[c][ky * 3 + kx][g * 16]);
                    float wv[16];
                    *reinterpret_cast<float4*>(&wv[0])  = wp[0];
                    *reinterpret_cast<float4*>(&wv[4])  = wp[1];
                    *reinterpret_cast<float4*>(&wv[8])  = wp[2];
                    *reinterpret_cast<float4*>(&wv[12]) = wp[3];
#pragma unroll
                    for (int o = 0; o < 16; o++) {
                        acc[0][o] += iv0 * wv[o];
                        acc[1][o] += iv1 * wv[o];
                        acc[2][o] += iv2 * wv[o];
                        acc[3][o] += iv3 * wv[o];
                    }
                }
            }
        }
        __syncthreads();
    }

#pragma unroll
    for (int d = 0; d < 4; d++) {
        int y = by0 + ybase + d;
        int xg = bx0 + pcol;
#pragma unroll
        for (int o = 0; o < 16; o++) {
            int gc = g * 16 + o;
            size_t off = (size_t)(b * 64 + gc) * HWN + y * WW + xg;
            out[off] = acc[d][o] + x[off];
        }
    }
}

// ---------------- launch ----------------
extern "C" void kernel_launch(void* const* d_in, const int* in_sizes, int n_in,
                              void* d_out, int out_size) {
    const float* x      = (const float*)d_in[0];
    const float* bridge = (const float*)d_in[1];
    const float* Wsub   = (const float*)d_in[2];
    const float* Wcb    = (const float*)d_in[3];
    float* out = (float*)d_out;

    transpose_w_kernel<<<288, 256>>>(Wsub, Wcb);
    conv1_kernel<<<dim3(8, 8, 8), 256>>>(x, bridge);
    reduce_kernel<<<dim3(NCHUNK, BB), 256>>>(bridge);
    solve_kernel<<<BB, 256>>>();
    conv2_kernel<<<dim3(16, 16, 8), 256>>>(x, out);
}